// round 16
// baseline (speedup 1.0000x reference)
#include <cuda_runtime.h>
#include <cuda_bf16.h>

// Problem constants
#define Nn 8
#define Cc 256
#define Tt 1024
#define Vv 25
#define Hh 8
#define Dd 64
#define HC 512

typedef unsigned int u32;
typedef unsigned long long u64;
typedef __nv_bfloat16 bf16;

// Precomputed globals
__device__ float g_q[HC * Vv];
__device__ float g_k[HC * Vv];
// attn, bf16, padded [8][32][40] (AT[h][v][u] = attn[h][u][v]); uint4 view
__device__ uint4 g_ATb4[1280];
// per-row Wo scales: s_wo[r] = max|Wo[r,:]| / 127
__device__ float g_swo[256];
// Wo int8 in mma-fragment order: fb = kc*32 + wm*4 + mt*2 + ks ; [fb][lane] uint4
__device__ uint4 g_WoI[256 * 32];

// ---------------- helpers ----------------
__device__ __forceinline__ void mma16(float* c, u32 a0, u32 a1, u32 a2, u32 a3,
                                      u32 b0, u32 b1) {
    asm("mma.sync.aligned.m16n8k16.row.col.f32.bf16.bf16.f32 "
        "{%0,%1,%2,%3}, {%4,%5,%6,%7}, {%8,%9}, {%0,%1,%2,%3};"
        : "+f"(c[0]), "+f"(c[1]), "+f"(c[2]), "+f"(c[3])
        : "r"(a0), "r"(a1), "r"(a2), "r"(a3), "r"(b0), "r"(b1));
}
__device__ __forceinline__ void mma_s8(int* c, u32 a0, u32 a1, u32 a2, u32 a3,
                                       u32 b0, u32 b1) {
    asm("mma.sync.aligned.m16n8k32.row.col.s32.s8.s8.s32 "
        "{%0,%1,%2,%3}, {%4,%5,%6,%7}, {%8,%9}, {%0,%1,%2,%3};"
        : "+r"(c[0]), "+r"(c[1]), "+r"(c[2]), "+r"(c[3])
        : "r"(a0), "r"(a1), "r"(a2), "r"(a3), "r"(b0), "r"(b1));
}
__device__ __forceinline__ void ldsm4(u32& r0, u32& r1, u32& r2, u32& r3, u32 a) {
    asm volatile("ldmatrix.sync.aligned.m8n8.x4.shared.b16 {%0,%1,%2,%3}, [%4];"
                 : "=r"(r0), "=r"(r1), "=r"(r2), "=r"(r3) : "r"(a));
}
__device__ __forceinline__ u32 lds32(u32 a) {
    u32 r; asm volatile("ld.shared.b32 %0, [%1];" : "=r"(r) : "r"(a)); return r;
}
__device__ __forceinline__ void sts32(u32 a, u32 v) {
    asm volatile("st.shared.b32 [%0], %1;" :: "r"(a), "r"(v));
}
__device__ __forceinline__ u32 smem_u32(const void* p) {
    return (u32)__cvta_generic_to_shared(p);
}
__device__ __forceinline__ int q8(float x, float inv) {
    int q = __float2int_rn(x * inv);
    return max(-127, min(127, q));
}

// SMEM byte offsets (main kernel)
#define OFF_BV    0        // 64 fp32
#define OFF_BO    256      // 256 fp32 -> 1280
#define OFF_SWO   1280     // 256 fp32 -> 2304
#define OFF_SMAX  2304     // pad to 2432
#define OFF_ZP    2432     // bf16 [104][520] = 108160 -> 110592
#define OFF_FT    2432     // bf16 [104][72] (V-stage union)
#define OFF_WVS   17408    // bf16 [64][72]  (V-stage union)
#define OFF_Z8    110592   // int8 [104][528] = 54912 -> 165504
#define OFF_AT    165504   // bf16 [8][32][40] = 20480 -> 185984
#define OFF_VS    185984   // bf16 [64][136]   = 17408 -> 203392
#define SMEM_MAIN 203392

#define NTHREADS 512

// ---------------------------------------------------------------------------
// Kernel 1: q/k GEMV, warp-per-5-outputs. 640 blocks x 8 warps.
// ---------------------------------------------------------------------------
__global__ void qk_kernel(const float* __restrict__ tf,
                          const float* __restrict__ Wq, const float* __restrict__ bq,
                          const float* __restrict__ Wk, const float* __restrict__ bk) {
    extern __shared__ float tf_s[];
    for (int idx = threadIdx.x; idx < HC * Vv; idx += blockDim.x) tf_s[idx] = tf[idx];
    __syncthreads();

    int wid = threadIdx.x >> 5, lane = threadIdx.x & 31;
    int gw = blockIdx.x * 8 + wid;
    int which = gw >= 2560;
    int rowid = gw - which * 2560;
    int hc = rowid / 5;
    int u0 = (rowid - hc * 5) * 5;
    const float* wrow = (which ? Wk : Wq) + hc * 512;

    float acc[5] = {0, 0, 0, 0, 0};
#pragma unroll
    for (int i = 0; i < 16; i++) {
        int k = i * 32 + lane;
        float w = wrow[k];
        const float* tb = tf_s + k * Vv + u0;
#pragma unroll
        for (int j = 0; j < 5; j++) acc[j] += w * tb[j];
    }
#pragma unroll
    for (int j = 0; j < 5; j++)
#pragma unroll
        for (int off = 16; off; off >>= 1)
            acc[j] += __shfl_xor_sync(0xFFFFFFFF, acc[j], off);

    if (lane == 0) {
        float b = (which ? bk : bq)[hc];
        float* dst = (which ? g_k : g_q) + hc * Vv + u0;
#pragma unroll
        for (int j = 0; j < 5; j++) dst[j] = acc[j] + b;
    }
}

// ---------------------------------------------------------------------------
// Kernel 2: energy + softmax -> g_ATb4. One block (1 warp) per head.
// ---------------------------------------------------------------------------
__global__ void attn_kernel() {
    __shared__ float q_s[Dd * Vv];
    __shared__ float k_s[Dd * Vv];
    const int h = blockIdx.x;
    const int t = threadIdx.x;

    for (int i = t; i < Dd * Vv; i += 32) {
        q_s[i] = g_q[h * Dd * Vv + i];
        k_s[i] = g_k[h * Dd * Vv + i];
    }
    u32* atz = (u32*)g_ATb4 + h * 640;
    for (int i = t; i < 640; i += 32) atz[i] = 0;
    __syncwarp();

    if (t < Vv) {
        float e[Vv];
#pragma unroll
        for (int j = 0; j < Vv; j++) e[j] = 0.f;
        for (int c = 0; c < Dd; c++) {
            float qv = q_s[c * Vv + t];
#pragma unroll
            for (int j = 0; j < Vv; j++) e[j] += qv * k_s[c * Vv + j];
        }
        float m = -1e30f;
#pragma unroll
        for (int j = 0; j < Vv; j++) { e[j] *= 0.125f; m = fmaxf(m, e[j]); }
        float ssum = 0.f;
#pragma unroll
        for (int j = 0; j < Vv; j++) { e[j] = expf(e[j] - m); ssum += e[j]; }
        float inv = 1.f / ssum;
        bf16* atb = (bf16*)g_ATb4;
#pragma unroll
        for (int j = 0; j < Vv; j++)
            atb[h * 1280 + j * 40 + t] = __float2bfloat16(e[j] * inv);
    }
}

// ---------------------------------------------------------------------------
// Kernel 2a: per-row Wo scale. 32 blocks x 256 (one warp per row).
// ---------------------------------------------------------------------------
__global__ void wo_scale(const float* __restrict__ Wo) {
    int wid = threadIdx.x >> 5, lane = threadIdx.x & 31;
    int row = blockIdx.x * 8 + wid;
    float m = 0.f;
    for (int i = lane; i < 512; i += 32) m = fmaxf(m, fabsf(Wo[row * 512 + i]));
#pragma unroll
    for (int off = 16; off; off >>= 1)
        m = fmaxf(m, __shfl_xor_sync(0xFFFFFFFF, m, off));
    if (lane == 0) g_swo[row] = m * (1.f / 127.f);
}

// ---------------------------------------------------------------------------
// Kernel 2b: Wo -> int8 fragment-order prep. fb = kc*32 + wm*4 + mt*2 + ks.
// 32 blocks x 256 threads = 8192 lanes.
// ---------------------------------------------------------------------------
__global__ void wo_prep(const float* __restrict__ Wo) {
    int t = blockIdx.x * 256 + threadIdx.x;
    int lane = t & 31;
    int fb = t >> 5;
    int ks = fb & 1, mt = (fb >> 1) & 1, wm = (fb >> 2) & 7, kc = fb >> 5;
    int r = wm * 32 + mt * 16;
    int kb = kc * 64 + ks * 32;
    int g = lane >> 2, li = lane & 3;
    int row0 = r + g, row1 = r + g + 8;

    float s0 = g_swo[row0], s1 = g_swo[row1];
    float i0 = s0 > 0.f ? 1.f / s0 : 0.f;
    float i1 = s1 > 0.f ? 1.f / s1 : 0.f;

    const float* p0 = Wo + (size_t)row0 * 512 + kb + li * 4;
    const float* p1 = Wo + (size_t)row1 * 512 + kb + li * 4;

    uint4 v;
    v.x = (u32)(q8(p0[0], i0) & 0xff) | ((u32)(q8(p0[1], i0) & 0xff) << 8)
        | ((u32)(q8(p0[2], i0) & 0xff) << 16) | ((u32)(q8(p0[3], i0) & 0xff) << 24);
    v.y = (u32)(q8(p1[0], i1) & 0xff) | ((u32)(q8(p1[1], i1) & 0xff) << 8)
        | ((u32)(q8(p1[2], i1) & 0xff) << 16) | ((u32)(q8(p1[3], i1) & 0xff) << 24);
    v.z = (u32)(q8(p0[16], i0) & 0xff) | ((u32)(q8(p0[17], i0) & 0xff) << 8)
        | ((u32)(q8(p0[18], i0) & 0xff) << 16) | ((u32)(q8(p0[19], i0) & 0xff) << 24);
    v.w = (u32)(q8(p1[16], i1) & 0xff) | ((u32)(q8(p1[17], i1) & 0xff) << 8)
        | ((u32)(q8(p1[18], i1) & 0xff) << 16) | ((u32)(q8(p1[19], i1) & 0xff) << 24);
    g_WoI[fb * 32 + lane] = v;
}

// ---------------------------------------------------------------------------
// Kernel 3 (main): one block per (n, 100 cols). 512 threads / 16 warps.
// V + Z in bf16 mma; main GEMM in int8 mma (m16n8k32), barrier-free.
// ---------------------------------------------------------------------------
__global__ void __launch_bounds__(NTHREADS, 1)
main_kernel(const float* __restrict__ f, const float* __restrict__ Wv,
            const float* __restrict__ bv, const float* __restrict__ bo,
            float* __restrict__ out) {
    extern __shared__ char smem_c[];
    float* bv_s  = (float*)(smem_c + OFF_BV);
    float* bo_s  = (float*)(smem_c + OFF_BO);
    float* swo_s = (float*)(smem_c + OFF_SWO);
    float* smax_s = (float*)(smem_c + OFF_SMAX);
    bf16* Zpp  = (bf16*)(smem_c + OFF_ZP);     // [104][520]
    uint4* AT4 = (uint4*)(smem_c + OFF_AT);    // [8][32][40] bf16 as 1280 uint4
    bf16* Vp   = (bf16*)(smem_c + OFF_VS);     // [64][136]
    bf16* FTp  = (bf16*)(smem_c + OFF_FT);     // [104][72]  (V-stage)
    bf16* Wvp  = (bf16*)(smem_c + OFF_WVS);    // [64][72]   (V-stage)
    const u32 sbase = smem_u32(smem_c);

    const int tid  = threadIdx.x;
    const int lane = tid & 31;
    const int wid  = tid >> 5;          // 0..15
    const int g    = lane >> 2;
    const int li   = lane & 3;
    const int n    = blockIdx.x >> 8;
    const int ct   = blockIdx.x & 255;

    // ldmatrix per-lane address patterns
    const int lq = lane >> 3, lr = lane & 7;
    const int arow = ((lq & 1) << 3) + lr;
    const int acol = (lq >> 1) << 4;
    const int brow = ((lq >> 1) << 3) + lr;
    const int bcol = (lq & 1) << 4;

    // ---- init ----
    for (int i = tid; i < 1280; i += NTHREADS) AT4[i] = g_ATb4[i];
    for (int i = tid; i < 4352; i += NTHREADS) ((u32*)Vp)[i]  = 0;
    for (int i = tid; i < 3744; i += NTHREADS) ((u32*)FTp)[i] = 0;
    if (tid < 64) bv_s[tid] = bv[tid];
    if (tid < 256) bo_s[tid] = bo[tid];
    if (tid >= 256 && tid < 512) swo_s[tid - 256] = g_swo[tid - 256];
    if (tid == 0) smax_s[0] = 0.f;
    __syncthreads();

    // ================= Stage V: V[64c][100col] = Wv @ F + bv =================
    const int v_mt  = wid & 3;
    const int v_nt0 = (wid >> 2) * 4;
    float vacc[4][4];
#pragma unroll
    for (int i = 0; i < 4; i++)
#pragma unroll
        for (int j = 0; j < 4; j++) vacc[i][j] = 0.f;

    const float4* f4base = (const float4*)(f + (size_t)n * 6553600 + (size_t)ct * 100);
    const u32 aW_base = sbase + OFF_WVS + (u32)(v_mt * 16 + arow) * 144 + acol;
    const u32 bF_base = sbase + OFF_FT + (u32)brow * 144 + bcol + (u32)v_nt0 * 1152;

    for (int kc = 0; kc < 4; kc++) {
        for (int idx4 = tid; idx4 < 1600; idx4 += NTHREADS) {
            int r = idx4 / 25, q = idx4 - r * 25;
            float4 v4 = f4base[(size_t)(kc * 64 + r) * 6400 + q];
            bf16* p = FTp + (q * 4) * 72 + r;
            p[0]   = __float2bfloat16(v4.x);
            p[72]  = __float2bfloat16(v4.y);
            p[144] = __float2bfloat16(v4.z);
            p[216] = __float2bfloat16(v4.w);
        }
        for (int idx4 = tid; idx4 < 1024; idx4 += NTHREADS) {
            int row = idx4 >> 4, j = idx4 & 15;
            float4 v4 = *(const float4*)(Wv + row * 256 + kc * 64 + j * 4);
            __nv_bfloat162* p = (__nv_bfloat162*)(Wvp + row * 72 + j * 4);
            p[0] = __nv_bfloat162(__float2bfloat16(v4.x), __float2bfloat16(v4.y));
            p[1] = __nv_bfloat162(__float2bfloat16(v4.z), __float2bfloat16(v4.w));
        }
        __syncthreads();
#pragma unroll
        for (int ks = 0; ks < 4; ks++) {
            u32 koff = ks * 32;
            u32 a0, a1, a2, a3;
            u32 bz[8];
            ldsm4(a0, a1, a2, a3, aW_base + koff);
            ldsm4(bz[0], bz[1], bz[2], bz[3], bF_base + koff);
            ldsm4(bz[4], bz[5], bz[6], bz[7], bF_base + 2304 + koff);
#pragma unroll
            for (int i = 0; i < 4; i++) {
                int nt = v_nt0 + i;
                if (nt < 13)
                    mma16(vacc[i], a0, a1, a2, a3, bz[2 * i], bz[2 * i + 1]);
            }
        }
        __syncthreads();
    }
    {
        int r0 = v_mt * 16 + g;
        float bv0 = bv_s[r0], bv1 = bv_s[r0 + 8];
#pragma unroll
        for (int i = 0; i < 4; i++) {
            int nt = v_nt0 + i;
            int col0 = nt * 8 + li * 2;
            if (nt < 13 && col0 < 100) {
                int tl = col0 / 25, u = col0 - tl * 25;
                Vp[r0 * 136 + tl * 32 + u]       = __float2bfloat16(vacc[i][0] + bv0);
                Vp[(r0 + 8) * 136 + tl * 32 + u] = __float2bfloat16(vacc[i][2] + bv1);
                int c1 = col0 + 1;
                int tl1 = c1 / 25, u1 = c1 - tl1 * 25;
                Vp[r0 * 136 + tl1 * 32 + u1]       = __float2bfloat16(vacc[i][1] + bv0);
                Vp[(r0 + 8) * 136 + tl1 * 32 + u1] = __float2bfloat16(vacc[i][3] + bv1);
            }
        }
    }
    __syncthreads();

    // ================= Z-gen (all 8 heads) + local |z| max =================
    float zmax = 0.f;
    {
        const int z_tl = wid & 3;
        const int z_c  = wid >> 2;
        const u32 aV_base = sbase + OFF_VS + (u32)(z_c * 16 + arow) * 272
                            + (u32)z_tl * 64 + acol;
        const u32 bA_base = sbase + OFF_AT + (u32)brow * 80 + bcol;
        const int c0 = z_c * 16 + g;

        for (int h = 0; h < 8; h++) {
            float zacc[4][4];
#pragma unroll
            for (int nt = 0; nt < 4; nt++)
#pragma unroll
                for (int j = 0; j < 4; j++) zacc[nt][j] = 0.f;
#pragma unroll
            for (int ks = 0; ks < 2; ks++) {
                u32 koff = ks * 32;
                u32 a0, a1, a2, a3;
                u32 bz[8];
                ldsm4(a0, a1, a2, a3, aV_base + koff);
                ldsm4(bz[0], bz[1], bz[2], bz[3], bA_base + h * 2560 + koff);
                ldsm4(bz[4], bz[5], bz[6], bz[7], bA_base + h * 2560 + 1280 + koff);
#pragma unroll
                for (int nt = 0; nt < 4; nt++)
                    mma16(zacc[nt], a0, a1, a2, a3, bz[2 * nt], bz[2 * nt + 1]);
            }
            int kbase = h * 64 + c0;
#pragma unroll
            for (int nt = 0; nt < 4; nt++) {
                int v0 = nt * 8 + 2 * li;
                if (v0 < 25) {
                    int col = z_tl * 25 + v0;
                    zmax = fmaxf(zmax, fmaxf(fabsf(zacc[nt][0]), fabsf(zacc[nt][2])));
                    Zpp[col * 520 + kbase]     = __float2bfloat16(zacc[nt][0]);
                    Zpp[col * 520 + kbase + 8] = __float2bfloat16(zacc[nt][2]);
                }
                if (v0 + 1 < 25) {
                    int col = z_tl * 25 + v0 + 1;
                    zmax = fmaxf(zmax, fmaxf(fabsf(zacc[nt][1]), fabsf(zacc[nt][3])));
                    Zpp[col * 520 + kbase]     = __float2bfloat16(zacc[nt][1]);
                    Zpp[col * 520 + kbase + 8] = __float2bfloat16(zacc[nt][3]);
                }
            }
        }
    }
    // warp-reduce zmax, lane0 atomics to smem
#pragma unroll
    for (int off = 16; off; off >>= 1)
        zmax = fmaxf(zmax, __shfl_xor_sync(0xFFFFFFFF, zmax, off));
    if (lane == 0) atomicMax((int*)smax_s, __float_as_int(zmax));
    __syncthreads();   // Zpp + smax complete

    // ================= Quantize Z -> int8 Z8[col][k] (stride 528) ============
    const float smax = smax_s[0];
    const float s_z = smax * (1.f / 127.f);
    {
        const float qinv = smax > 1e-20f ? 127.f / smax : 0.f;
        for (int idx = tid; idx < 104 * 128; idx += NTHREADS) {
            int col = idx >> 7, kq = idx & 127;
            u32 a = sbase + OFF_ZP + (u32)col * 1040 + (u32)kq * 8;
            u32 w0 = lds32(a), w1 = lds32(a + 4);
            float f0 = __uint_as_float(w0 << 16);
            float f1 = __uint_as_float(w0 & 0xffff0000u);
            float f2 = __uint_as_float(w1 << 16);
            float f3 = __uint_as_float(w1 & 0xffff0000u);
            u32 packed = (u32)(q8(f0, qinv) & 0xff)
                       | ((u32)(q8(f1, qinv) & 0xff) << 8)
                       | ((u32)(q8(f2, qinv) & 0xff) << 16)
                       | ((u32)(q8(f3, qinv) & 0xff) << 24);
            sts32(sbase + OFF_Z8 + (u32)col * 528 + (u32)kq * 4, packed);
        }
    }
    __syncthreads();   // Z8 ready — LAST barrier; main GEMM barrier-free

    // ================= Main GEMM (int8): out = Wo @ Z, K=512 ================
    // warp (wm 0..7, wn 0..1): m-tiles {2wm,2wm+1}; n-tiles wn?{7..12}:{0..6}
    const int wm = wid & 7, wn = wid >> 3;
    const int nb = wn * 7;
    const int ncnt = wn ? 6 : 7;
    int macc[2][7][4];
#pragma unroll
    for (int mt = 0; mt < 2; mt++)
#pragma unroll
        for (int j = 0; j < 7; j++)
#pragma unroll
            for (int q = 0; q < 4; q++) macc[mt][j][q] = 0;

    u32 bRow[7];
#pragma unroll
    for (int j = 0; j < 7; j++)
        bRow[j] = sbase + OFF_Z8 + (u32)((nb + j) * 8 + g) * 528 + (u32)li * 4;

    const uint4* WF = g_WoI + (u32)wm * 4 * 32 + lane;  // [kc*1024 + mt*64 + ks*32]
    uint4 a0c = WF[0], a1c = WF[64];   // fi=0

#pragma unroll
    for (int fi = 0; fi < 16; fi++) {
        // prefetch a-frags for fi+1
        int nfi = fi < 15 ? fi + 1 : 15;
        int nkc = nfi >> 1, nks = nfi & 1;
        uint4 a0n = WF[nkc * 1024 + nks * 32];
        uint4 a1n = WF[nkc * 1024 + 64 + nks * 32];

        u32 koff = (u32)fi * 32;
        u32 b0[7], b1[7];
#pragma unroll
        for (int j = 0; j < 7; j++) {
            if (j < ncnt) {
                b0[j] = lds32(bRow[j] + koff);
                b1[j] = lds32(bRow[j] + koff + 16);
            }
        }
#pragma unroll
        for (int j = 0; j < 7; j++) {
            if (j < ncnt) {
                mma_s8(macc[0][j], a0c.x, a0c.y, a0c.z, a0c.w, b0[j], b1[j]);
                mma_s8(macc[1][j], a1c.x, a1c.y, a1c.z, a1c.w, b0[j], b1[j]);
            }
        }
        a0c = a0n; a1c = a1n;
    }

    // ================= Epilogue: dequant + bo + residual f ===================
    {
        const size_t base = (size_t)n * 6553600 + (size_t)ct * 100;
#pragma unroll
        for (int mt = 0; mt < 2; mt++) {
            int r0 = wm * 32 + mt * 16 + g;
            float fct0 = swo_s[r0] * s_z, fct1 = swo_s[r0 + 8] * s_z;
            float bo0 = bo_s[r0], bo1 = bo_s[r0 + 8];
#pragma unroll
            for (int j = 0; j < 7; j++) {
                if (j < ncnt) {
                    int col0 = (nb + j) * 8 + li * 2;
                    if (col0 < 100) {
                        size_t a0 = base + (size_t)r0 * 25600 + col0;
                        float2 fv0 = *(const float2*)(f + a0);
                        float2 ov0;
                        ov0.x = fct0 * (float)macc[mt][j][0] + bo0 + fv0.x;
                        ov0.y = fct0 * (float)macc[mt][j][1] + bo0 + fv0.y;
                        *(float2*)(out + a0) = ov0;
                        size_t a2 = base + (size_t)(r0 + 8) * 25600 + col0;
                        float2 fv2 = *(const float2*)(f + a2);
                        float2 ov2;
                        ov2.x = fct1 * (float)macc[mt][j][2] + bo1 + fv2.x;
                        ov2.y = fct1 * (float)macc[mt][j][3] + bo1 + fv2.y;
                        *(float2*)(out + a2) = ov2;
                    }
                }
            }
        }
    }
}

// ---------------------------------------------------------------------------
extern "C" void kernel_launch(void* const* d_in, const int* in_sizes, int n_in,
                              void* d_out, int out_size) {
    const float* feature = (const float*)d_in[0];
    const float* tf      = (const float*)d_in[1];
    const float* Wq      = (const float*)d_in[2];
    const float* bq      = (const float*)d_in[3];
    const float* Wk      = (const float*)d_in[4];
    const float* bk      = (const float*)d_in[5];
    const float* Wv      = (const float*)d_in[6];
    const float* bv      = (const float*)d_in[7];
    const float* Wo      = (const float*)d_in[8];
    const float* bo      = (const float*)d_in[9];
    float* out = (float*)d_out;

    const size_t qk_smem = (size_t)HC * Vv * sizeof(float);

    cudaFuncSetAttribute((const void*)qk_kernel,
                         cudaFuncAttributeMaxDynamicSharedMemorySize, (int)qk_smem);
    cudaFuncSetAttribute((const void*)main_kernel,
                         cudaFuncAttributeMaxDynamicSharedMemorySize, SMEM_MAIN);

    qk_kernel<<<640, 256, qk_smem>>>(tf, Wq, bq, Wk, bk);
    attn_kernel<<<8, 32>>>();
    wo_scale<<<32, 256>>>(Wo);
    wo_prep<<<32, 256>>>(Wo);
    main_kernel<<<Nn * 256, NTHREADS, SMEM_MAIN>>>(feature, Wv, bv, bo, out);
}

// round 17
// speedup vs baseline: 1.6818x; 1.6818x over previous
#include <cuda_runtime.h>
#include <cuda_bf16.h>

// Problem constants
#define Nn 8
#define Cc 256
#define Tt 1024
#define Vv 25
#define Hh 8
#define Dd 64
#define HC 512

typedef unsigned int u32;
typedef unsigned long long u64;
typedef __nv_bfloat16 bf16;

// Precomputed globals
__device__ float g_q[HC * Vv];
__device__ float g_k[HC * Vv];
// attn, bf16, padded [8][32][40] (AT[h][v][u] = attn[h][u][v]); uint4 view
__device__ uint4 g_ATb4[1280];
// Wo in mma-fragment order: [kc(8)][wm(8)][mt(2)][ks(4)][lane(32)] x uint4
__device__ uint4 g_WoF[512 * 32];

// ---------------- helpers ----------------
__device__ __forceinline__ void mma16(float* c, u32 a0, u32 a1, u32 a2, u32 a3,
                                      u32 b0, u32 b1) {
    asm("mma.sync.aligned.m16n8k16.row.col.f32.bf16.bf16.f32 "
        "{%0,%1,%2,%3}, {%4,%5,%6,%7}, {%8,%9}, {%0,%1,%2,%3};"
        : "+f"(c[0]), "+f"(c[1]), "+f"(c[2]), "+f"(c[3])
        : "r"(a0), "r"(a1), "r"(a2), "r"(a3), "r"(b0), "r"(b1));
}
__device__ __forceinline__ void ldsm4(u32& r0, u32& r1, u32& r2, u32& r3, u32 a) {
    asm volatile("ldmatrix.sync.aligned.m8n8.x4.shared.b16 {%0,%1,%2,%3}, [%4];"
                 : "=r"(r0), "=r"(r1), "=r"(r2), "=r"(r3) : "r"(a));
}
__device__ __forceinline__ void ldsm2(u32& r0, u32& r1, u32 a) {
    asm volatile("ldmatrix.sync.aligned.m8n8.x2.shared.b16 {%0,%1}, [%2];"
                 : "=r"(r0), "=r"(r1) : "r"(a));
}
__device__ __forceinline__ u32 smem_u32(const void* p) {
    return (u32)__cvta_generic_to_shared(p);
}

// SMEM byte offsets (main kernel)
#define OFF_BV   0        // 64 fp32
#define OFF_BO   256      // 256 fp32
#define OFF_ZP   1280     // bf16 [104][520] = 108160 B (all-head Z^T)
#define OFF_FT   1280     // bf16 [104][72] (V-stage only, union w/ ZP)
#define OFF_WVS  16256    // bf16 [64][72]  (V-stage only, union w/ ZP)
#define OFF_AT   109440   // bf16 [8][32][40] = 20480 B
#define OFF_VS   129920   // bf16 [64][136]   = 17408 B
#define SMEM_MAIN 147328

#define NTHREADS 512

// ---------------------------------------------------------------------------
// Kernel 1: q/k GEMV. 80 blocks x 8 warps; each warp does 8 groups of 5 outputs.
// tf staged in SMEM once per block (80 x 51KB = 4MB total traffic).
// ---------------------------------------------------------------------------
__global__ void qk_kernel(const float* __restrict__ tf,
                          const float* __restrict__ Wq, const float* __restrict__ bq,
                          const float* __restrict__ Wk, const float* __restrict__ bk) {
    extern __shared__ float tf_s[];
    for (int idx = threadIdx.x; idx < HC * Vv; idx += blockDim.x) tf_s[idx] = tf[idx];
    __syncthreads();

    int wid = threadIdx.x >> 5, lane = threadIdx.x & 31;

#pragma unroll 1
    for (int rep = 0; rep < 8; rep++) {
        int gw = blockIdx.x * 64 + wid * 8 + rep;   // 0..5119
        int which = gw >= 2560;
        int rowid = gw - which * 2560;
        int hc = rowid / 5;
        int u0 = (rowid - hc * 5) * 5;
        const float* wrow = (which ? Wk : Wq) + hc * 512;

        float acc[5] = {0, 0, 0, 0, 0};
#pragma unroll
        for (int i = 0; i < 16; i++) {
            int k = i * 32 + lane;
            float w = wrow[k];
            const float* tb = tf_s + k * Vv + u0;
#pragma unroll
            for (int j = 0; j < 5; j++) acc[j] += w * tb[j];
        }
#pragma unroll
        for (int j = 0; j < 5; j++)
#pragma unroll
            for (int off = 16; off; off >>= 1)
                acc[j] += __shfl_xor_sync(0xFFFFFFFF, acc[j], off);

        if (lane == 0) {
            float b = (which ? bk : bq)[hc];
            float* dst = (which ? g_k : g_q) + hc * Vv + u0;
#pragma unroll
            for (int j = 0; j < 5; j++) dst[j] = acc[j] + b;
        }
    }
}

// ---------------------------------------------------------------------------
// Kernel 2: energy + softmax -> g_ATb4. One block (1 warp) per head.
// ---------------------------------------------------------------------------
__global__ void attn_kernel() {
    __shared__ float q_s[Dd * Vv];
    __shared__ float k_s[Dd * Vv];
    const int h = blockIdx.x;
    const int t = threadIdx.x;   // 0..31

    for (int i = t; i < Dd * Vv; i += 32) {
        q_s[i] = g_q[h * Dd * Vv + i];
        k_s[i] = g_k[h * Dd * Vv + i];
    }
    // zero this head's padded bf16 attn slice (640 u32)
    u32* atz = (u32*)g_ATb4 + h * 640;
    for (int i = t; i < 640; i += 32) atz[i] = 0;
    __syncwarp();

    if (t < Vv) {
        float e[Vv];
#pragma unroll
        for (int j = 0; j < Vv; j++) e[j] = 0.f;
        for (int c = 0; c < Dd; c++) {
            float qv = q_s[c * Vv + t];
#pragma unroll
            for (int j = 0; j < Vv; j++) e[j] += qv * k_s[c * Vv + j];
        }
        float m = -1e30f;
#pragma unroll
        for (int j = 0; j < Vv; j++) { e[j] *= 0.125f; m = fmaxf(m, e[j]); }
        float ssum = 0.f;
#pragma unroll
        for (int j = 0; j < Vv; j++) { e[j] = expf(e[j] - m); ssum += e[j]; }
        float inv = 1.f / ssum;
        // AT[h][v=j][u=t] = attn[h][u=t][j]
        bf16* atb = (bf16*)g_ATb4;
#pragma unroll
        for (int j = 0; j < Vv; j++)
            atb[h * 1280 + j * 40 + t] = __float2bfloat16(e[j] * inv);
    }
}

// ---------------------------------------------------------------------------
// Kernel 2b: Wo -> bf16 fragment-order prep. fb = ((kc*8+wm)*2+mt)*4+ks
// ---------------------------------------------------------------------------
__global__ void wo_prep(const float* __restrict__ Wo) {
    int t = blockIdx.x * 256 + threadIdx.x;
    int lane = t & 31;
    int fb = t >> 5;
    int ks = fb & 3, mt = (fb >> 2) & 1, wm = (fb >> 3) & 7, kc = fb >> 6;
    int r = wm * 32 + mt * 16;
    int kb = kc * 64 + ks * 16;
    int g = lane >> 2, li = lane & 3;

    const float* p00 = Wo + (size_t)(r + g) * 512 + kb + 2 * li;
    const float* p10 = Wo + (size_t)(r + g + 8) * 512 + kb + 2 * li;

    __nv_bfloat162 h0(__float2bfloat16(p00[0]), __float2bfloat16(p00[1]));
    __nv_bfloat162 h1(__float2bfloat16(p10[0]), __float2bfloat16(p10[1]));
    __nv_bfloat162 h2(__float2bfloat16(p00[8]), __float2bfloat16(p00[9]));
    __nv_bfloat162 h3(__float2bfloat16(p10[8]), __float2bfloat16(p10[9]));

    uint4 v;
    v.x = *(u32*)&h0; v.y = *(u32*)&h1; v.z = *(u32*)&h2; v.w = *(u32*)&h3;
    g_WoF[fb * 32 + lane] = v;
}

// ---------------------------------------------------------------------------
// Kernel 3 (main): one block per (n, 100 cols). 512 threads / 16 warps.
// Batched b-fragment LDSM; barrier-free main GEMM; Wo a-frags via LDG.
// ---------------------------------------------------------------------------
__global__ void __launch_bounds__(NTHREADS, 1)
main_kernel(const float* __restrict__ f, const float* __restrict__ Wv,
            const float* __restrict__ bv, const float* __restrict__ bo,
            float* __restrict__ out) {
    extern __shared__ char smem_c[];
    float* bv_s = (float*)(smem_c + OFF_BV);
    float* bo_s = (float*)(smem_c + OFF_BO);
    bf16* Zpp  = (bf16*)(smem_c + OFF_ZP);     // [104][520]
    uint4* AT4 = (uint4*)(smem_c + OFF_AT);    // [8][32][40] bf16 as 1280 uint4
    bf16* Vp   = (bf16*)(smem_c + OFF_VS);     // [64][136]
    bf16* FTp  = (bf16*)(smem_c + OFF_FT);     // [104][72]  (V-stage)
    bf16* Wvp  = (bf16*)(smem_c + OFF_WVS);    // [64][72]   (V-stage)
    const u32 sbase = smem_u32(smem_c);

    const int tid  = threadIdx.x;
    const int lane = tid & 31;
    const int wid  = tid >> 5;          // 0..15
    const int g    = lane >> 2;
    const int li   = lane & 3;
    const int n    = blockIdx.x >> 8;
    const int ct   = blockIdx.x & 255;

    // ldmatrix per-lane address patterns
    const int lq = lane >> 3, lr = lane & 7;
    const int arow = ((lq & 1) << 3) + lr;   // A: tiles (m, m+8) x (k, k+8)
    const int acol = (lq >> 1) << 4;         // bytes
    const int brow = ((lq >> 1) << 3) + lr;  // B: tiles (n)x(k,k+8),(n+8)x(k,k+8)
    const int bcol = (lq & 1) << 4;          // bytes

    // ---- init: copy padded bf16 attn, zero V/FT pads, load biases ----
    for (int i = tid; i < 1280; i += NTHREADS) AT4[i] = g_ATb4[i];
    for (int i = tid; i < 4352; i += NTHREADS) ((u32*)Vp)[i]  = 0;
    for (int i = tid; i < 3744; i += NTHREADS) ((u32*)FTp)[i] = 0;
    if (tid < 64) bv_s[tid] = bv[tid];
    if (tid < 256) bo_s[tid] = bo[tid];
    __syncthreads();

    // ================= Stage V: V[64c][100col] = Wv @ F + bv =================
    const int v_mt  = wid & 3;           // m-tile (16 rows)
    const int v_nt0 = (wid >> 2) * 4;    // nt group {0,4,8,12}
    float vacc[4][4];
#pragma unroll
    for (int i = 0; i < 4; i++)
#pragma unroll
        for (int j = 0; j < 4; j++) vacc[i][j] = 0.f;

    const float4* f4base = (const float4*)(f + (size_t)n * 6553600 + (size_t)ct * 100);
    const u32 aW_base = sbase + OFF_WVS + (u32)(v_mt * 16 + arow) * 144 + acol;
    const u32 bF_base = sbase + OFF_FT + (u32)brow * 144 + bcol + (u32)v_nt0 * 1152;

    for (int kc = 0; kc < 4; kc++) {
        // stage F^T: FT[col][k] bf16 (stride 72)
        for (int idx4 = tid; idx4 < 1600; idx4 += NTHREADS) {
            int r = idx4 / 25, q = idx4 - r * 25;
            float4 v4 = f4base[(size_t)(kc * 64 + r) * 6400 + q];
            bf16* p = FTp + (q * 4) * 72 + r;
            p[0]   = __float2bfloat16(v4.x);
            p[72]  = __float2bfloat16(v4.y);
            p[144] = __float2bfloat16(v4.z);
            p[216] = __float2bfloat16(v4.w);
        }
        // stage Wv chunk: Wv_s[c][k] bf16 (stride 72)
        for (int idx4 = tid; idx4 < 1024; idx4 += NTHREADS) {
            int row = idx4 >> 4, j = idx4 & 15;
            float4 v4 = *(const float4*)(Wv + row * 256 + kc * 64 + j * 4);
            __nv_bfloat162* p = (__nv_bfloat162*)(Wvp + row * 72 + j * 4);
            p[0] = __nv_bfloat162(__float2bfloat16(v4.x), __float2bfloat16(v4.y));
            p[1] = __nv_bfloat162(__float2bfloat16(v4.z), __float2bfloat16(v4.w));
        }
        __syncthreads();
#pragma unroll
        for (int ks = 0; ks < 4; ks++) {
            u32 koff = ks * 32;
            u32 a0, a1, a2, a3;
            u32 bz[8];
            ldsm4(a0, a1, a2, a3, aW_base + koff);
            ldsm4(bz[0], bz[1], bz[2], bz[3], bF_base + koff);
            ldsm4(bz[4], bz[5], bz[6], bz[7], bF_base + 2304 + koff);
#pragma unroll
            for (int i = 0; i < 4; i++) {
                int nt = v_nt0 + i;
                if (nt < 13)
                    mma16(vacc[i], a0, a1, a2, a3, bz[2 * i], bz[2 * i + 1]);
            }
        }
        __syncthreads();
    }
    // V epilogue -> V_s bf16 [c][tl*32+u] (stride 136)
    {
        int r0 = v_mt * 16 + g;
        float bv0 = bv_s[r0], bv1 = bv_s[r0 + 8];
#pragma unroll
        for (int i = 0; i < 4; i++) {
            int nt = v_nt0 + i;
            int col0 = nt * 8 + li * 2;
            if (nt < 13 && col0 < 100) {
                int tl = col0 / 25, u = col0 - tl * 25;
                Vp[r0 * 136 + tl * 32 + u]       = __float2bfloat16(vacc[i][0] + bv0);
                Vp[(r0 + 8) * 136 + tl * 32 + u] = __float2bfloat16(vacc[i][2] + bv1);
                int c1 = col0 + 1;
                int tl1 = c1 / 25, u1 = c1 - tl1 * 25;
                Vp[r0 * 136 + tl1 * 32 + u1]       = __float2bfloat16(vacc[i][1] + bv0);
                Vp[(r0 + 8) * 136 + tl1 * 32 + u1] = __float2bfloat16(vacc[i][3] + bv1);
            }
        }
    }
    __syncthreads();   // V_s ready; FT/Wv region dead -> ZP may be written

    // ================= Z-gen (all 8 heads, barrier-free) =================
    // Zp[col][k] bf16, col = tl*25+v (0..99), k = h*64 + c, stride 520
    {
        const int z_tl = wid & 3;        // t-slice
        const int z_c  = wid >> 2;       // c-quarter (16 rows)
        const u32 aV_base = sbase + OFF_VS + (u32)(z_c * 16 + arow) * 272
                            + (u32)z_tl * 64 + acol;
        const u32 bA_base = sbase + OFF_AT + (u32)brow * 80 + bcol;
        const int c0 = z_c * 16 + g;

        for (int h = 0; h < 8; h++) {
            float zacc[4][4];
#pragma unroll
            for (int nt = 0; nt < 4; nt++)
#pragma unroll
                for (int j = 0; j < 4; j++) zacc[nt][j] = 0.f;
#pragma unroll
            for (int ks = 0; ks < 2; ks++) {
                u32 koff = ks * 32;
                u32 a0, a1, a2, a3;
                u32 bz[8];
                ldsm4(a0, a1, a2, a3, aV_base + koff);
                ldsm4(bz[0], bz[1], bz[2], bz[3], bA_base + h * 2560 + koff);
                ldsm4(bz[4], bz[5], bz[6], bz[7], bA_base + h * 2560 + 1280 + koff);
#pragma unroll
                for (int nt = 0; nt < 4; nt++)
                    mma16(zacc[nt], a0, a1, a2, a3, bz[2 * nt], bz[2 * nt + 1]);
            }
            int kbase = h * 64 + c0;
#pragma unroll
            for (int nt = 0; nt < 4; nt++) {
                int v0 = nt * 8 + 2 * li;
                if (v0 < 25) {
                    int col = z_tl * 25 + v0;
                    Zpp[col * 520 + kbase]     = __float2bfloat16(zacc[nt][0]);
                    Zpp[col * 520 + kbase + 8] = __float2bfloat16(zacc[nt][2]);
                }
                if (v0 + 1 < 25) {
                    int col = z_tl * 25 + v0 + 1;
                    Zpp[col * 520 + kbase]     = __float2bfloat16(zacc[nt][1]);
                    Zpp[col * 520 + kbase + 8] = __float2bfloat16(zacc[nt][3]);
                }
            }
        }
    }
    __syncthreads();   // Zp complete — LAST barrier; main GEMM is barrier-free

    // ================= Main GEMM: out[256][100] = Wo[256][512] @ Z ===========
    // warp (wm 0..7, wn 0..1): m-tiles {2wm, 2wm+1}; n-tiles wn?{7..12}:{0..6}
    // a-frags via LDG from fragment-ordered g_WoF; b-frags batched per ks.
    const int wm = wid & 7, wn = wid >> 3;
    const int nb = wn * 7;
    const int ncnt = wn ? 6 : 7;
    float macc[2][7][4];
#pragma unroll
    for (int mt = 0; mt < 2; mt++)
#pragma unroll
        for (int j = 0; j < 7; j++)
#pragma unroll
            for (int q = 0; q < 4; q++) macc[mt][j][q] = 0.f;

    const u32 bZ_base = sbase + OFF_ZP + (u32)(nb * 8 + brow) * 1040 + bcol;
    const uint4* WF = g_WoF + (u32)wm * 256 + lane;   // [kc*2048 + mt*128 + ks*32]

    uint4 acur0 = WF[0];
    uint4 acur1 = WF[128];

#pragma unroll
    for (int kc = 0; kc < 8; kc++) {
        const u32 bZ = bZ_base + (u32)kc * 128;
#pragma unroll
        for (int ks = 0; ks < 4; ks++) {
            // prefetch a-frags for next (kc,ks)
            int fi = kc * 4 + ks;
            int nfi = fi < 31 ? fi + 1 : 31;
            int nkc = nfi >> 2, nks = nfi & 3;
            uint4 anxt0 = WF[nkc * 2048 + nks * 32];
            uint4 anxt1 = WF[nkc * 2048 + 128 + nks * 32];

            u32 koff = ks * 32;
            // batched b-fragment loads (load-use distance maximized)
            u32 bz[14];
            ldsm4(bz[0], bz[1], bz[2], bz[3], bZ + koff);
            ldsm4(bz[4], bz[5], bz[6], bz[7], bZ + 16640u + koff);
            ldsm4(bz[8], bz[9], bz[10], bz[11], bZ + 33280u + koff);
            if (ncnt == 7) ldsm2(bz[12], bz[13], bZ + 49920u + koff);

#pragma unroll
            for (int p = 0; p < 3; p++) {
                mma16(macc[0][2 * p],     acur0.x, acur0.y, acur0.z, acur0.w,
                      bz[4 * p], bz[4 * p + 1]);
                mma16(macc[1][2 * p],     acur1.x, acur1.y, acur1.z, acur1.w,
                      bz[4 * p], bz[4 * p + 1]);
                mma16(macc[0][2 * p + 1], acur0.x, acur0.y, acur0.z, acur0.w,
                      bz[4 * p + 2], bz[4 * p + 3]);
                mma16(macc[1][2 * p + 1], acur1.x, acur1.y, acur1.z, acur1.w,
                      bz[4 * p + 2], bz[4 * p + 3]);
            }
            if (ncnt == 7) {
                mma16(macc[0][6], acur0.x, acur0.y, acur0.z, acur0.w, bz[12], bz[13]);
                mma16(macc[1][6], acur1.x, acur1.y, acur1.z, acur1.w, bz[12], bz[13]);
            }
            acur0 = anxt0;
            acur1 = anxt1;
        }
    }

    // ================= Epilogue: + bo + residual f (float2 stores) ============
    {
        const size_t base = (size_t)n * 6553600 + (size_t)ct * 100;
#pragma unroll
        for (int mt = 0; mt < 2; mt++) {
            int r0 = wm * 32 + mt * 16 + g;
            float bo0 = bo_s[r0], bo1 = bo_s[r0 + 8];
#pragma unroll
            for (int j = 0; j < 7; j++) {
                if (j < ncnt) {
                    int col0 = (nb + j) * 8 + li * 2;
                    if (col0 < 100) {
                        size_t a0 = base + (size_t)r0 * 25600 + col0;
                        float2 fv0 = *(const float2*)(f + a0);
                        float2 ov0;
                        ov0.x = macc[mt][j][0] + bo0 + fv0.x;
                        ov0.y = macc[mt][j][1] + bo0 + fv0.y;
                        *(float2*)(out + a0) = ov0;
                        size_t a2 = base + (size_t)(r0 + 8) * 25600 + col0;
                        float2 fv2 = *(const float2*)(f + a2);
                        float2 ov2;
                        ov2.x = macc[mt][j][2] + bo1 + fv2.x;
                        ov2.y = macc[mt][j][3] + bo1 + fv2.y;
                        *(float2*)(out + a2) = ov2;
                    }
                }
            }
        }
    }
}

// ---------------------------------------------------------------------------
extern "C" void kernel_launch(void* const* d_in, const int* in_sizes, int n_in,
                              void* d_out, int out_size) {
    const float* feature = (const float*)d_in[0];
    const float* tf      = (const float*)d_in[1];
    const float* Wq      = (const float*)d_in[2];
    const float* bq      = (const float*)d_in[3];
    const float* Wk      = (const float*)d_in[4];
    const float* bk      = (const float*)d_in[5];
    const float* Wv      = (const float*)d_in[6];
    const float* bv      = (const float*)d_in[7];
    const float* Wo      = (const float*)d_in[8];
    const float* bo      = (const float*)d_in[9];
    float* out = (float*)d_out;

    const size_t qk_smem = (size_t)HC * Vv * sizeof(float);

    cudaFuncSetAttribute((const void*)qk_kernel,
                         cudaFuncAttributeMaxDynamicSharedMemorySize, (int)qk_smem);
    cudaFuncSetAttribute((const void*)main_kernel,
                         cudaFuncAttributeMaxDynamicSharedMemorySize, SMEM_MAIN);

    qk_kernel<<<80, 256, qk_smem>>>(tf, Wq, bq, Wk, bk);
    attn_kernel<<<8, 32>>>();
    wo_prep<<<64, 256>>>(Wo);
    main_kernel<<<Nn * 256, NTHREADS, SMEM_MAIN>>>(feature, Wv, bv, bo, out);
}